// round 13
// baseline (speedup 1.0000x reference)
#include <cuda_runtime.h>
#include <math.h>

#define HH 128
#define WW 128
#define HW (HH * WW)
#define BB 2

typedef unsigned int u32;

// ---------------- scratch (static device allocations; no runtime alloc) ----
__device__ float g_feat1[BB * 64 * HW];     // after conv1+lrelu (tf32-rounded)
__device__ float g_feat2[BB * 64 * HW];     // after conv2+lrelu (tf32-rounded)
__device__ float g_om[BB * 216 * HW];       // raw conv_om output (fp32)
__device__ float g_dcnwB[8 * 9 * 8 * 32 * 2];   // dcn weights, MMA B-frag order
// conv weights in per-lane MMA B-frag order: [z][chunk][tap][nt][lane][2]
__device__ float g_wc1[2 * 17 * 2304];
__device__ float g_wc2[2 * 8 * 2304];
__device__ float g_wom[7 * 8 * 2304];

// ---------------- cp.async helpers ----------------------------------------
__device__ __forceinline__ u32 s2u(const void* p) {
    return (u32)__cvta_generic_to_shared(p);
}
__device__ __forceinline__ void cpasync4(u32 dst, const void* src, int srcsize) {
    asm volatile("cp.async.ca.shared.global [%0], [%1], 4, %2;\n"
                 :: "r"(dst), "l"(src), "r"(srcsize));
}
__device__ __forceinline__ void cpasync16(u32 dst, const void* src) {
    asm volatile("cp.async.cg.shared.global [%0], [%1], 16;\n"
                 :: "r"(dst), "l"(src));
}
__device__ __forceinline__ void cpcommit() {
    asm volatile("cp.async.commit_group;\n");
}
template <int N>
__device__ __forceinline__ void cpwait() {
    asm volatile("cp.async.wait_group %0;\n" :: "n"(N));
}

// ---------------- tf32 helpers --------------------------------------------
__device__ __forceinline__ u32 tf32r(float x) {
    u32 u; asm("cvt.rna.tf32.f32 %0, %1;" : "=r"(u) : "f"(x)); return u;
}
__device__ __forceinline__ void mma_tf32(float d[4], const u32 a[4], u32 b0, u32 b1) {
    asm volatile(
        "mma.sync.aligned.m16n8k8.row.col.f32.tf32.tf32.f32 "
        "{%0,%1,%2,%3}, {%4,%5,%6,%7}, {%8,%9}, {%0,%1,%2,%3};\n"
        : "+f"(d[0]), "+f"(d[1]), "+f"(d[2]), "+f"(d[3])
        : "r"(a[0]), "r"(a[1]), "r"(a[2]), "r"(a[3]), "r"(b0), "r"(b1));
}

// ---------------------------------------------------------------------------
// tf32 implicit-GEMM 3x3 conv. A patches staged via cp.async (double-buffer);
// B weights read directly from GLOBAL in per-lane fragment order (L1-hot,
// one float2 per (tap, nt)). doCvt=0 when the input is already tf32-rounded;
// roundStore=1 tf32-rounds the output (bit-identical for downstream convs).
// ---------------------------------------------------------------------------
#define A_PLANE (10 * 20)
#define A_BYTES (8 * A_PLANE * 4)
#define FRAG_CHUNK (9 * 4 * 64)         // floats per chunk of frag weights
#define NSTGA 6

__global__ void __launch_bounds__(256, 2) conv_mma_kernel(
    const float* __restrict__ inA, int nA,
    const float* __restrict__ inB, int nB,
    const float* __restrict__ inC, int nC,
    const float* __restrict__ wfrag,
    const float* __restrict__ bias,
    float* __restrict__ out, int OC, int chunks, int zTiles,
    int doLrelu, int doCvt, int roundStore)
{
    const int bz = blockIdx.z;
    const int b  = bz / zTiles;
    const int zi = bz - b * zTiles;
    const int ocBase = zi * 32;

    const int tid  = threadIdx.x;
    const int lane = tid & 31;
    const int warp = tid >> 5;
    const int gid  = lane >> 2;
    const int tig  = lane & 3;

    const int h0 = blockIdx.y * 8;
    const int w0 = blockIdx.x * 16;
    const int ICt = nA + nB + nC;

    __shared__ float sA[2][8][10][20];

    int  goff[NSTGA];
    int  ginb[NSTGA];
    u32  sofs[NSTGA];
    int  plane[NSTGA];
    int  nElems = 0;
#pragma unroll
    for (int s = 0; s < NSTGA; s++) {
        int i = tid + s * 256;
        if (i < 8 * 10 * 18) {
            int p = i / 180, rem = i - p * 180;
            int r = rem / 18, c = rem - r * 18;
            int gy = h0 + r - 1, gx = w0 + c - 1;
            ginb[s] = (gy >= 0 && gy < HH && gx >= 0 && gx < WW) ? 1 : 0;
            int gyc = min(max(gy, 0), HH - 1);
            int gxc = min(max(gx, 0), WW - 1);
            goff[s]  = gyc * WW + gxc;
            sofs[s]  = (u32)(((p * 10 + r) * 20 + c) * 4);
            plane[s] = p;
            nElems = s + 1;
        }
    }
    const u32 sAbase = s2u(&sA[0][0][0][0]);
    const float* wz = wfrag + (size_t)zi * chunks * FRAG_CHUNK;

    auto fetchAsync = [&](int buf, int ch) {
#pragma unroll
        for (int s = 0; s < NSTGA; s++) {
            if (s < nElems) {
                int ic = ch * 8 + plane[s];
                const float* base;
                if (ic < nA)            base = inA + ((size_t)(b * nA + ic)) * HW;
                else if (ic < nA + nB)  base = inB + ((size_t)(b * nB + (ic - nA))) * HW;
                else if (ic < ICt)      base = inC + ((size_t)(b * nC + (ic - nA - nB))) * HW;
                else                    base = inA;
                int sz = (ic < ICt && ginb[s]) ? 4 : 0;
                cpasync4(sAbase + (u32)buf * A_BYTES + sofs[s], base + goff[s], sz);
            }
        }
    };

    float acc[4][4];
#pragma unroll
    for (int t = 0; t < 4; t++)
#pragma unroll
        for (int q = 0; q < 4; q++) acc[t][q] = 0.f;

    fetchAsync(0, 0);
    cpcommit();

    int buf = 0;
    for (int ch = 0; ch < chunks; ch++) {
        if (ch + 1 < chunks) {
            fetchAsync(buf ^ 1, ch + 1);
            cpcommit();
            cpwait<1>();
        } else {
            cpwait<0>();
        }
        __syncthreads();

        const float (*PA)[10][20] = sA[buf];
        const float* fragC = wz + (size_t)ch * FRAG_CHUNK;

#pragma unroll
        for (int tap = 0; tap < 9; tap++) {
            const int dy = tap / 3, dx = tap % 3;
            u32 a[4];
            if (doCvt) {
                a[0] = tf32r(PA[tig    ][warp + dy][gid     + dx]);
                a[1] = tf32r(PA[tig    ][warp + dy][gid + 8 + dx]);
                a[2] = tf32r(PA[tig + 4][warp + dy][gid     + dx]);
                a[3] = tf32r(PA[tig + 4][warp + dy][gid + 8 + dx]);
            } else {
                a[0] = __float_as_uint(PA[tig    ][warp + dy][gid     + dx]);
                a[1] = __float_as_uint(PA[tig    ][warp + dy][gid + 8 + dx]);
                a[2] = __float_as_uint(PA[tig + 4][warp + dy][gid     + dx]);
                a[3] = __float_as_uint(PA[tig + 4][warp + dy][gid + 8 + dx]);
            }
#pragma unroll
            for (int t = 0; t < 4; t++) {
                float2 bb = *(const float2*)&fragC[((tap * 4 + t) * 32 + lane) * 2];
                mma_tf32(acc[t], a, __float_as_uint(bb.x), __float_as_uint(bb.y));
            }
        }

        __syncthreads();
        buf ^= 1;
    }

    const int py  = h0 + warp;
    const int px0 = w0 + gid;
#pragma unroll
    for (int t = 0; t < 4; t++) {
        int oc = ocBase + t * 8 + 2 * tig;
#pragma unroll
        for (int e = 0; e < 2; e++) {
            int oce = oc + e;
            if (oce < OC) {
                float bv = bias[oce];
                float v0 = acc[t][e]     + bv;
                float v1 = acc[t][e + 2] + bv;
                if (doLrelu) {
                    v0 = (v0 >= 0.f) ? v0 : 0.1f * v0;
                    v1 = (v1 >= 0.f) ? v1 : 0.1f * v1;
                }
                if (roundStore) {
                    v0 = __uint_as_float(tf32r(v0));
                    v1 = __uint_as_float(tf32r(v1));
                }
                float* dst = out + ((size_t)(b * OC + oce)) * HW + py * WW;
                dst[px0]     = v0;
                dst[px0 + 8] = v1;
            }
        }
    }
}

// ---------------------------------------------------------------------------
// Repack conv weights [oc][ic][tap] -> per-lane B-frag order
// dst[(((z*chunks + ch)*9 + tap)*4 + nt)*64 + lane*2 + pair]
//   pair p: B[kk = (lane&3)+4p][n = lane>>2], oc = z*32 + nt*8 + n,
//   ic = ch*8 + kk; tf32-rounded; zero beyond IC/OC.
// ---------------------------------------------------------------------------
__global__ void repack_convw_frag(const float* __restrict__ w, float* __restrict__ dst,
                                  int IC, int OC, int chunks, int zTiles)
{
    int total = zTiles * chunks * FRAG_CHUNK;
    int i = blockIdx.x * blockDim.x + threadIdx.x;
    if (i >= total) return;
    int pair = i & 1;
    int t    = i >> 1;
    int lane = t & 31;  t >>= 5;
    int nt   = t & 3;   t >>= 2;
    int tap  = t % 9;   t /= 9;
    int ch   = t % chunks;
    int z    = t / chunks;
    int kk = (lane & 3) + 4 * pair;
    int n  = lane >> 2;
    int ic = ch * 8 + kk;
    int oc = z * 32 + nt * 8 + n;
    float v = 0.f;
    if (ic < IC && oc < OC)
        v = w[((size_t)oc * IC + ic) * 9 + tap];
    u32 u; asm("cvt.rna.tf32.f32 %0, %1;" : "=r"(u) : "f"(v));
    dst[i] = __uint_as_float(u);
}

// ---------------------------------------------------------------------------
// Repack dcn_w [o][g*8+c][k] into per-lane MMA B-fragment order (proven R12).
// ---------------------------------------------------------------------------
__global__ void repack_dcnwB_kernel(const float* __restrict__ w)
{
    int i = blockIdx.x * blockDim.x + threadIdx.x;
    if (i >= 8 * 9 * 8 * 32 * 2) return;
    int pair = i & 1;
    int t    = i >> 1;
    int lane = t & 31;  t >>= 5;
    int nt   = t & 7;   t >>= 3;
    int k    = t % 9;
    int g    = t / 9;
    int c  = (lane & 3) + 4 * pair;
    int oc = nt * 8 + (lane >> 2);
    float v = w[(size_t)oc * 576 + (g * 8 + c) * 9 + k];
    u32 u; asm("cvt.rna.tf32.f32 %0, %1;" : "=r"(u) : "f"(v));
    g_dcnwB[i] = __uint_as_float(u);
}

// ---------------------------------------------------------------------------
// Modulated deformable conv with tf32 MMA accumulate (proven R12, unchanged).
// ---------------------------------------------------------------------------
__global__ void __launch_bounds__(128, 2) dcn_mma_kernel(
    const float* __restrict__ feat,
    const float* __restrict__ om,
    const float* __restrict__ flows,
    const float* __restrict__ bias,
    float* __restrict__ out)
{
    const int b  = blockIdx.z;
    const int tx = threadIdx.x;
    const int ty = threadIdx.y;
    const int tid = ty * 16 + tx;
    const int lane = tid & 31;
    const int warpid = tid >> 5;
    const int gid = lane >> 2;
    const int tig = lane & 3;
    const int h = blockIdx.y * 8 + ty;
    const int w = blockIdx.x * 16 + tx;
    const int pix = h * WW + w;

    __shared__ float sVal[4][9][32][9];

    float acc[2][8][4];
#pragma unroll
    for (int m = 0; m < 2; m++)
#pragma unroll
        for (int n = 0; n < 8; n++)
#pragma unroll
            for (int q = 0; q < 4; q++) acc[m][n][q] = 0.f;

    const float flowX = flows[(b * 2 + 0) * HW + pix];
    const float flowY = flows[(b * 2 + 1) * HW + pix];
    const float* omb = om   + (size_t)b * 216 * HW;
    const float* fb  = feat + (size_t)b * 64 * HW;

    for (int g = 0; g < 8; g++) {
        float offv[18], mskv[9];
#pragma unroll
        for (int q = 0; q < 18; q++)
            offv[q] = omb[((size_t)(g * 18 + q)) * HW + pix];
#pragma unroll
        for (int q = 0; q < 9; q++)
            mskv[q] = omb[((size_t)(144 + g * 9 + q)) * HW + pix];

        const float* fgc = fb + (g * 8) * HW;

#pragma unroll
        for (int k = 0; k < 9; k++) {
            const int kh = k / 3, kw = k - kh * 3;
            float dy = offv[2 * k + 0] + flowY;
            float dx = offv[2 * k + 1] + flowX;
            float mv = mskv[k];
            mv = 1.f / (1.f + __expf(-mv));

            float y = (float)h - 1.f + (float)kh + dy;
            float x = (float)w - 1.f + (float)kw + dx;
            float y0f = floorf(y), x0f = floorf(x);
            int y0 = (int)y0f, x0 = (int)x0f;
            float fy = y - y0f, fx = x - x0f;

            float w00 = (1.f - fy) * (1.f - fx);
            float w01 = (1.f - fy) * fx;
            float w10 = fy * (1.f - fx);
            float w11 = fy * fx;

            const bool iy0 = (y0 >= 0) && (y0 < HH);
            const bool iy1 = (y0 + 1 >= 0) && (y0 + 1 < HH);
            const bool ix0 = (x0 >= 0) && (x0 < WW);
            const bool ix1 = (x0 + 1 >= 0) && (x0 + 1 < WW);
            w00 = (iy0 && ix0) ? w00 * mv : 0.f;
            w01 = (iy0 && ix1) ? w01 * mv : 0.f;
            w10 = (iy1 && ix0) ? w10 * mv : 0.f;
            w11 = (iy1 && ix1) ? w11 * mv : 0.f;

            int yc0 = min(max(y0, 0), HH - 1);
            int yc1 = min(max(y0 + 1, 0), HH - 1);
            int xc0 = min(max(x0, 0), WW - 1);
            int xc1 = min(max(x0 + 1, 0), WW - 1);
            int i00 = yc0 * WW + xc0, i01 = yc0 * WW + xc1;
            int i10 = yc1 * WW + xc0, i11 = yc1 * WW + xc1;

#pragma unroll
            for (int c = 0; c < 8; c++) {
                const float* fc = fgc + c * HW;
                float val = w00 * fc[i00] + w01 * fc[i01]
                          + w10 * fc[i10] + w11 * fc[i11];
                sVal[warpid][k][lane][c] = __uint_as_float(tf32r(val));
            }
        }
        __syncwarp();

        const float* fragBase = g_dcnwB + (size_t)g * 9 * 8 * 64;
#pragma unroll
        for (int k = 0; k < 9; k++) {
            const float (*V)[9] = sVal[warpid][k];
            u32 a0[4], a1[4];
            a0[0] = __float_as_uint(V[gid     ][tig    ]);
            a0[1] = __float_as_uint(V[gid + 8 ][tig    ]);
            a0[2] = __float_as_uint(V[gid     ][tig + 4]);
            a0[3] = __float_as_uint(V[gid + 8 ][tig + 4]);
            a1[0] = __float_as_uint(V[gid + 16][tig    ]);
            a1[1] = __float_as_uint(V[gid + 24][tig    ]);
            a1[2] = __float_as_uint(V[gid + 16][tig + 4]);
            a1[3] = __float_as_uint(V[gid + 24][tig + 4]);
#pragma unroll
            for (int nt = 0; nt < 8; nt++) {
                float2 bb = *(const float2*)&fragBase[((k * 8 + nt) * 32 + lane) * 2];
                u32 b0 = __float_as_uint(bb.x);
                u32 b1 = __float_as_uint(bb.y);
                mma_tf32(acc[0][nt], a0, b0, b1);
                mma_tf32(acc[1][nt], a1, b0, b1);
            }
        }
        __syncwarp();
    }

    const int h0 = blockIdx.y * 8;
    const int w0 = blockIdx.x * 16;
#pragma unroll
    for (int m = 0; m < 2; m++) {
        int r0 = warpid * 32 + m * 16 + gid;
        int r1 = r0 + 8;
        int hA = h0 + (r0 >> 4), wA = w0 + (r0 & 15);
        int hB = h0 + (r1 >> 4), wB2 = w0 + (r1 & 15);
#pragma unroll
        for (int nt = 0; nt < 8; nt++) {
            int oc0 = nt * 8 + 2 * tig;
#pragma unroll
            for (int e = 0; e < 2; e++) {
                int oc = oc0 + e;
                float bv = bias[oc];
                float vA = acc[m][nt][e]     + bv;
                float vB = acc[m][nt][e + 2] + bv;
                vA = (vA >= 0.f) ? vA : 0.1f * vA;
                vB = (vB >= 0.f) ? vB : 0.1f * vB;
                out[((size_t)(b * 64 + oc)) * HW + hA * WW + wA]  = vA;
                out[((size_t)(b * 64 + oc)) * HW + hB * WW + wB2] = vB;
            }
        }
    }
}

// ---------------------------------------------------------------------------
extern "C" void kernel_launch(void* const* d_in, const int* in_sizes, int n_in,
                              void* d_out, int out_size)
{
    const float* ref_fea2X      = (const float*)d_in[0];
    const float* ref_fea2X_flow = (const float*)d_in[1];
    const float* lr_shake_fea   = (const float*)d_in[2];
    const float* flows          = (const float*)d_in[3];
    const float* w1             = (const float*)d_in[4];
    const float* b1             = (const float*)d_in[5];
    const float* w2             = (const float*)d_in[6];
    const float* b2             = (const float*)d_in[7];
    const float* w_om           = (const float*)d_in[8];
    const float* b_om           = (const float*)d_in[9];
    const float* dcn_w          = (const float*)d_in[10];
    const float* dcn_b          = (const float*)d_in[11];
    float* out = (float*)d_out;

    float *feat1, *feat2, *omb, *wc1, *wc2, *wom;
    cudaGetSymbolAddress((void**)&feat1, g_feat1);
    cudaGetSymbolAddress((void**)&feat2, g_feat2);
    cudaGetSymbolAddress((void**)&omb,   g_om);
    cudaGetSymbolAddress((void**)&wc1,   g_wc1);
    cudaGetSymbolAddress((void**)&wc2,   g_wc2);
    cudaGetSymbolAddress((void**)&wom,   g_wom);

    // weight repacks (independent of activations)
    repack_dcnwB_kernel<<<(8 * 9 * 8 * 32 * 2 + 255) / 256, 256>>>(dcn_w);
    repack_convw_frag<<<(2 * 17 * FRAG_CHUNK + 255) / 256, 256>>>(w1,   wc1, 130, 64, 17, 2);
    repack_convw_frag<<<(2 * 8  * FRAG_CHUNK + 255) / 256, 256>>>(w2,   wc2, 64,  64,  8, 2);
    repack_convw_frag<<<(7 * 8  * FRAG_CHUNK + 255) / 256, 256>>>(w_om, wom, 64, 216, 8, 7);

    dim3 thrM(256);
    // conv1: external inputs -> cvt on; output tf32-rounded
    conv_mma_kernel<<<dim3(8, 16, BB * 2), thrM>>>(
        ref_fea2X_flow, 64, lr_shake_fea, 64, flows, 2,
        wc1, b1, feat1, 64, 17, 2, 1, 1, 1);
    // conv2: input already tf32 -> cvt off; output tf32-rounded
    conv_mma_kernel<<<dim3(8, 16, BB * 2), thrM>>>(
        feat1, 64, (const float*)0, 0, (const float*)0, 0,
        wc2, b2, feat2, 64, 8, 2, 1, 0, 1);
    // conv_om: input already tf32 -> cvt off; raw fp32 output
    conv_mma_kernel<<<dim3(8, 16, BB * 7), thrM>>>(
        feat2, 64, (const float*)0, 0, (const float*)0, 0,
        wom, b_om, omb, 216, 8, 7, 0, 0, 0);

    // modulated deformable conv + lrelu (tf32 MMA accumulate)
    dcn_mma_kernel<<<dim3(8, 16, BB), dim3(16, 8)>>>(ref_fea2X, omb, flows, dcn_b, out);
}

// round 14
// speedup vs baseline: 1.3271x; 1.3271x over previous
#include <cuda_runtime.h>
#include <math.h>

#define HH 128
#define WW 128
#define HW (HH * WW)
#define BB 2

typedef unsigned int u32;

// ---------------- scratch (static device allocations; no runtime alloc) ----
__device__ float g_feat1[BB * 64 * HW];     // after conv1+lrelu (tf32-rounded)
__device__ float g_feat2[BB * 64 * HW];     // after conv2+lrelu (tf32-rounded)
__device__ float g_om[BB * 216 * HW];       // raw conv_om output (fp32)
__device__ float g_dcnwB[8 * 9 * 8 * 32 * 2];   // dcn weights, MMA B-frag order
// repacked conv weights, tf32-rounded: [z][chunk][tap][k8][oc40]
__device__ float g_wc1[2 * 17 * 2880];
__device__ float g_wc2[2 * 8 * 2880];
__device__ float g_wom[7 * 8 * 2880];

// ---------------- cp.async helpers ----------------------------------------
__device__ __forceinline__ u32 s2u(const void* p) {
    return (u32)__cvta_generic_to_shared(p);
}
__device__ __forceinline__ void cpasync4(u32 dst, const void* src, int srcsize) {
    asm volatile("cp.async.ca.shared.global [%0], [%1], 4, %2;\n"
                 :: "r"(dst), "l"(src), "r"(srcsize));
}
__device__ __forceinline__ void cpasync16(u32 dst, const void* src) {
    asm volatile("cp.async.cg.shared.global [%0], [%1], 16;\n"
                 :: "r"(dst), "l"(src));
}
__device__ __forceinline__ void cpcommit() {
    asm volatile("cp.async.commit_group;\n");
}
template <int N>
__device__ __forceinline__ void cpwait() {
    asm volatile("cp.async.wait_group %0;\n" :: "n"(N));
}

// ---------------- tf32 helpers --------------------------------------------
__device__ __forceinline__ u32 tf32r(float x) {
    u32 u; asm("cvt.rna.tf32.f32 %0, %1;" : "=r"(u) : "f"(x)); return u;
}
__device__ __forceinline__ void mma_tf32(float d[4], const u32 a[4], u32 b0, u32 b1) {
    asm volatile(
        "mma.sync.aligned.m16n8k8.row.col.f32.tf32.tf32.f32 "
        "{%0,%1,%2,%3}, {%4,%5,%6,%7}, {%8,%9}, {%0,%1,%2,%3};\n"
        : "+f"(d[0]), "+f"(d[1]), "+f"(d[2]), "+f"(d[3])
        : "r"(a[0]), "r"(a[1]), "r"(a[2]), "r"(a[3]), "r"(b0), "r"(b1));
}

// ---------------------------------------------------------------------------
// tf32 implicit-GEMM 3x3 conv — R12 proven structure (A and B both staged via
// cp.async double-buffering). doCvt=0 when input activations are already
// tf32-rounded; roundStore=1 tf32-rounds the stored output (bit-identical
// for downstream convs that would round anyway).
// ---------------------------------------------------------------------------
#define A_PLANE (10 * 20)
#define A_BYTES (8 * A_PLANE * 4)
#define B_FLOATS (72 * 40)
#define B_BYTES (B_FLOATS * 4)
#define NSTGA 6

__global__ void __launch_bounds__(256, 2) conv_mma_kernel(
    const float* __restrict__ inA, int nA,
    const float* __restrict__ inB, int nB,
    const float* __restrict__ inC, int nC,
    const float* __restrict__ wrep,
    const float* __restrict__ bias,
    float* __restrict__ out, int OC, int chunks, int zTiles,
    int doLrelu, int doCvt, int roundStore)
{
    const int bz = blockIdx.z;
    const int b  = bz / zTiles;
    const int zi = bz - b * zTiles;
    const int ocBase = zi * 32;

    const int tid  = threadIdx.x;
    const int lane = tid & 31;
    const int warp = tid >> 5;
    const int gid  = lane >> 2;
    const int tig  = lane & 3;

    const int h0 = blockIdx.y * 8;
    const int w0 = blockIdx.x * 16;
    const int ICt = nA + nB + nC;

    __shared__ float sA[2][8][10][20];
    __shared__ float sB[2][72][40];

    int  goff[NSTGA];
    int  ginb[NSTGA];
    u32  sofs[NSTGA];
    int  plane[NSTGA];
    int  nElems = 0;
#pragma unroll
    for (int s = 0; s < NSTGA; s++) {
        int i = tid + s * 256;
        if (i < 8 * 10 * 18) {
            int p = i / 180, rem = i - p * 180;
            int r = rem / 18, c = rem - r * 18;
            int gy = h0 + r - 1, gx = w0 + c - 1;
            ginb[s] = (gy >= 0 && gy < HH && gx >= 0 && gx < WW) ? 1 : 0;
            int gyc = min(max(gy, 0), HH - 1);
            int gxc = min(max(gx, 0), WW - 1);
            goff[s]  = gyc * WW + gxc;
            sofs[s]  = (u32)(((p * 10 + r) * 20 + c) * 4);
            plane[s] = p;
            nElems = s + 1;
        }
    }
    const u32 sAbase = s2u(&sA[0][0][0][0]);
    const u32 sBbase = s2u(&sB[0][0][0]);
    const float* wz = wrep + (size_t)zi * chunks * B_FLOATS;

    auto fetchAsync = [&](int buf, int ch) {
#pragma unroll
        for (int s = 0; s < NSTGA; s++) {
            if (s < nElems) {
                int ic = ch * 8 + plane[s];
                const float* base;
                if (ic < nA)            base = inA + ((size_t)(b * nA + ic)) * HW;
                else if (ic < nA + nB)  base = inB + ((size_t)(b * nB + (ic - nA))) * HW;
                else if (ic < ICt)      base = inC + ((size_t)(b * nC + (ic - nA - nB))) * HW;
                else                    base = inA;
                int sz = (ic < ICt && ginb[s]) ? 4 : 0;
                cpasync4(sAbase + (u32)buf * A_BYTES + sofs[s], base + goff[s], sz);
            }
        }
        const float* wsrc = wz + (size_t)ch * B_FLOATS;
#pragma unroll
        for (int s = 0; s < 3; s++) {
            int g = tid + s * 256;
            if (g < B_FLOATS / 4)
                cpasync16(sBbase + (u32)buf * B_BYTES + (u32)g * 16, wsrc + g * 4);
        }
    };

    float acc[4][4];
#pragma unroll
    for (int t = 0; t < 4; t++)
#pragma unroll
        for (int q = 0; q < 4; q++) acc[t][q] = 0.f;

    fetchAsync(0, 0);
    cpcommit();

    int buf = 0;
    for (int ch = 0; ch < chunks; ch++) {
        if (ch + 1 < chunks) {
            fetchAsync(buf ^ 1, ch + 1);
            cpcommit();
            cpwait<1>();
        } else {
            cpwait<0>();
        }
        __syncthreads();

        const float (*PA)[10][20] = sA[buf];
        const float (*PB)[40]     = sB[buf];

#pragma unroll
        for (int tap = 0; tap < 9; tap++) {
            const int dy = tap / 3, dx = tap % 3;
            u32 a[4];
            if (doCvt) {
                a[0] = tf32r(PA[tig    ][warp + dy][gid     + dx]);
                a[1] = tf32r(PA[tig    ][warp + dy][gid + 8 + dx]);
                a[2] = tf32r(PA[tig + 4][warp + dy][gid     + dx]);
                a[3] = tf32r(PA[tig + 4][warp + dy][gid + 8 + dx]);
            } else {
                a[0] = __float_as_uint(PA[tig    ][warp + dy][gid     + dx]);
                a[1] = __float_as_uint(PA[tig    ][warp + dy][gid + 8 + dx]);
                a[2] = __float_as_uint(PA[tig + 4][warp + dy][gid     + dx]);
                a[3] = __float_as_uint(PA[tig + 4][warp + dy][gid + 8 + dx]);
            }
#pragma unroll
            for (int t = 0; t < 4; t++) {
                u32 b0 = __float_as_uint(PB[tap * 8 + tig    ][t * 8 + gid]);
                u32 b1 = __float_as_uint(PB[tap * 8 + tig + 4][t * 8 + gid]);
                mma_tf32(acc[t], a, b0, b1);
            }
        }

        __syncthreads();
        buf ^= 1;
    }

    const int py  = h0 + warp;
    const int px0 = w0 + gid;
#pragma unroll
    for (int t = 0; t < 4; t++) {
        int oc = ocBase + t * 8 + 2 * tig;
#pragma unroll
        for (int e = 0; e < 2; e++) {
            int oce = oc + e;
            if (oce < OC) {
                float bv = bias[oce];
                float v0 = acc[t][e]     + bv;
                float v1 = acc[t][e + 2] + bv;
                if (doLrelu) {
                    v0 = (v0 >= 0.f) ? v0 : 0.1f * v0;
                    v1 = (v1 >= 0.f) ? v1 : 0.1f * v1;
                }
                if (roundStore) {
                    v0 = __uint_as_float(tf32r(v0));
                    v1 = __uint_as_float(tf32r(v1));
                }
                float* dst = out + ((size_t)(b * OC + oce)) * HW + py * WW;
                dst[px0]     = v0;
                dst[px0 + 8] = v1;
            }
        }
    }
}

// ---------------------------------------------------------------------------
// Repack conv weights -> [z][chunk][tap][k8][oc40], tf32-rounded (R12 proven).
// ---------------------------------------------------------------------------
__global__ void repack_convw_kernel(const float* __restrict__ w, float* __restrict__ dst,
                                    int IC, int OC, int chunks, int zTiles)
{
    int total = zTiles * chunks * B_FLOATS;
    int i = blockIdx.x * blockDim.x + threadIdx.x;
    if (i >= total) return;
    int oc40 = i % 40;
    int row  = (i / 40) % 72;
    int ch   = (i / (40 * 72)) % chunks;
    int z    = i / (40 * 72 * chunks);
    int kk = row & 7, tap = row >> 3;
    int ic  = ch * 8 + kk;
    int ocg = z * 32 + oc40;
    float v = 0.f;
    if (oc40 < 32 && ic < IC && ocg < OC)
        v = w[((size_t)ocg * IC + ic) * 9 + tap];
    u32 u; asm("cvt.rna.tf32.f32 %0, %1;" : "=r"(u) : "f"(v));
    dst[i] = __uint_as_float(u);
}

// ---------------------------------------------------------------------------
// Repack dcn_w [o][g*8+c][k] into per-lane MMA B-fragment order (R12 proven).
// ---------------------------------------------------------------------------
__global__ void repack_dcnwB_kernel(const float* __restrict__ w)
{
    int i = blockIdx.x * blockDim.x + threadIdx.x;
    if (i >= 8 * 9 * 8 * 32 * 2) return;
    int pair = i & 1;
    int t    = i >> 1;
    int lane = t & 31;  t >>= 5;
    int nt   = t & 7;   t >>= 3;
    int k    = t % 9;
    int g    = t / 9;
    int c  = (lane & 3) + 4 * pair;
    int oc = nt * 8 + (lane >> 2);
    float v = w[(size_t)oc * 576 + (g * 8 + c) * 9 + k];
    u32 u; asm("cvt.rna.tf32.f32 %0, %1;" : "=r"(u) : "f"(v));
    g_dcnwB[i] = __uint_as_float(u);
}

// ---------------------------------------------------------------------------
// Modulated deformable conv with tf32 MMA accumulate (R12 proven, unchanged).
// ---------------------------------------------------------------------------
__global__ void __launch_bounds__(128, 2) dcn_mma_kernel(
    const float* __restrict__ feat,
    const float* __restrict__ om,
    const float* __restrict__ flows,
    const float* __restrict__ bias,
    float* __restrict__ out)
{
    const int b  = blockIdx.z;
    const int tx = threadIdx.x;
    const int ty = threadIdx.y;
    const int tid = ty * 16 + tx;
    const int lane = tid & 31;
    const int warpid = tid >> 5;
    const int gid = lane >> 2;
    const int tig = lane & 3;
    const int h = blockIdx.y * 8 + ty;
    const int w = blockIdx.x * 16 + tx;
    const int pix = h * WW + w;

    __shared__ float sVal[4][9][32][9];

    float acc[2][8][4];
#pragma unroll
    for (int m = 0; m < 2; m++)
#pragma unroll
        for (int n = 0; n < 8; n++)
#pragma unroll
            for (int q = 0; q < 4; q++) acc[m][n][q] = 0.f;

    const float flowX = flows[(b * 2 + 0) * HW + pix];
    const float flowY = flows[(b * 2 + 1) * HW + pix];
    const float* omb = om   + (size_t)b * 216 * HW;
    const float* fb  = feat + (size_t)b * 64 * HW;

    for (int g = 0; g < 8; g++) {
        float offv[18], mskv[9];
#pragma unroll
        for (int q = 0; q < 18; q++)
            offv[q] = omb[((size_t)(g * 18 + q)) * HW + pix];
#pragma unroll
        for (int q = 0; q < 9; q++)
            mskv[q] = omb[((size_t)(144 + g * 9 + q)) * HW + pix];

        const float* fgc = fb + (g * 8) * HW;

#pragma unroll
        for (int k = 0; k < 9; k++) {
            const int kh = k / 3, kw = k - kh * 3;
            float dy = offv[2 * k + 0] + flowY;
            float dx = offv[2 * k + 1] + flowX;
            float mv = mskv[k];
            mv = 1.f / (1.f + __expf(-mv));

            float y = (float)h - 1.f + (float)kh + dy;
            float x = (float)w - 1.f + (float)kw + dx;
            float y0f = floorf(y), x0f = floorf(x);
            int y0 = (int)y0f, x0 = (int)x0f;
            float fy = y - y0f, fx = x - x0f;

            float w00 = (1.f - fy) * (1.f - fx);
            float w01 = (1.f - fy) * fx;
            float w10 = fy * (1.f - fx);
            float w11 = fy * fx;

            const bool iy0 = (y0 >= 0) && (y0 < HH);
            const bool iy1 = (y0 + 1 >= 0) && (y0 + 1 < HH);
            const bool ix0 = (x0 >= 0) && (x0 < WW);
            const bool ix1 = (x0 + 1 >= 0) && (x0 + 1 < WW);
            w00 = (iy0 && ix0) ? w00 * mv : 0.f;
            w01 = (iy0 && ix1) ? w01 * mv : 0.f;
            w10 = (iy1 && ix0) ? w10 * mv : 0.f;
            w11 = (iy1 && ix1) ? w11 * mv : 0.f;

            int yc0 = min(max(y0, 0), HH - 1);
            int yc1 = min(max(y0 + 1, 0), HH - 1);
            int xc0 = min(max(x0, 0), WW - 1);
            int xc1 = min(max(x0 + 1, 0), WW - 1);
            int i00 = yc0 * WW + xc0, i01 = yc0 * WW + xc1;
            int i10 = yc1 * WW + xc0, i11 = yc1 * WW + xc1;

#pragma unroll
            for (int c = 0; c < 8; c++) {
                const float* fc = fgc + c * HW;
                float val = w00 * fc[i00] + w01 * fc[i01]
                          + w10 * fc[i10] + w11 * fc[i11];
                sVal[warpid][k][lane][c] = __uint_as_float(tf32r(val));
            }
        }
        __syncwarp();

        const float* fragBase = g_dcnwB + (size_t)g * 9 * 8 * 64;
#pragma unroll
        for (int k = 0; k < 9; k++) {
            const float (*V)[9] = sVal[warpid][k];
            u32 a0[4], a1[4];
            a0[0] = __float_as_uint(V[gid     ][tig    ]);
            a0[1] = __float_as_uint(V[gid + 8 ][tig    ]);
            a0[2] = __float_as_uint(V[gid     ][tig + 4]);
            a0[3] = __float_as_uint(V[gid + 8 ][tig + 4]);
            a1[0] = __float_as_uint(V[gid + 16][tig    ]);
            a1[1] = __float_as_uint(V[gid + 24][tig    ]);
            a1[2] = __float_as_uint(V[gid + 16][tig + 4]);
            a1[3] = __float_as_uint(V[gid + 24][tig + 4]);
#pragma unroll
            for (int nt = 0; nt < 8; nt++) {
                float2 bb = *(const float2*)&fragBase[((k * 8 + nt) * 32 + lane) * 2];
                u32 b0 = __float_as_uint(bb.x);
                u32 b1 = __float_as_uint(bb.y);
                mma_tf32(acc[0][nt], a0, b0, b1);
                mma_tf32(acc[1][nt], a1, b0, b1);
            }
        }
        __syncwarp();
    }

    const int h0 = blockIdx.y * 8;
    const int w0 = blockIdx.x * 16;
#pragma unroll
    for (int m = 0; m < 2; m++) {
        int r0 = warpid * 32 + m * 16 + gid;
        int r1 = r0 + 8;
        int hA = h0 + (r0 >> 4), wA = w0 + (r0 & 15);
        int hB = h0 + (r1 >> 4), wB2 = w0 + (r1 & 15);
#pragma unroll
        for (int nt = 0; nt < 8; nt++) {
            int oc0 = nt * 8 + 2 * tig;
#pragma unroll
            for (int e = 0; e < 2; e++) {
                int oc = oc0 + e;
                float bv = bias[oc];
                float vA = acc[m][nt][e]     + bv;
                float vB = acc[m][nt][e + 2] + bv;
                vA = (vA >= 0.f) ? vA : 0.1f * vA;
                vB = (vB >= 0.f) ? vB : 0.1f * vB;
                out[((size_t)(b * 64 + oc)) * HW + hA * WW + wA]  = vA;
                out[((size_t)(b * 64 + oc)) * HW + hB * WW + wB2] = vB;
            }
        }
    }
}

// ---------------------------------------------------------------------------
extern "C" void kernel_launch(void* const* d_in, const int* in_sizes, int n_in,
                              void* d_out, int out_size)
{
    const float* ref_fea2X      = (const float*)d_in[0];
    const float* ref_fea2X_flow = (const float*)d_in[1];
    const float* lr_shake_fea   = (const float*)d_in[2];
    const float* flows          = (const float*)d_in[3];
    const float* w1             = (const float*)d_in[4];
    const float* b1             = (const float*)d_in[5];
    const float* w2             = (const float*)d_in[6];
    const float* b2             = (const float*)d_in[7];
    const float* w_om           = (const float*)d_in[8];
    const float* b_om           = (const float*)d_in[9];
    const float* dcn_w          = (const float*)d_in[10];
    const float* dcn_b          = (const float*)d_in[11];
    float* out = (float*)d_out;

    float *feat1, *feat2, *omb, *wc1, *wc2, *wom;
    cudaGetSymbolAddress((void**)&feat1, g_feat1);
    cudaGetSymbolAddress((void**)&feat2, g_feat2);
    cudaGetSymbolAddress((void**)&omb,   g_om);
    cudaGetSymbolAddress((void**)&wc1,   g_wc1);
    cudaGetSymbolAddress((void**)&wc2,   g_wc2);
    cudaGetSymbolAddress((void**)&wom,   g_wom);

    // weight repacks (independent of activations)
    repack_dcnwB_kernel<<<(8 * 9 * 8 * 32 * 2 + 255) / 256, 256>>>(dcn_w);
    repack_convw_kernel<<<(2 * 17 * B_FLOATS + 255) / 256, 256>>>(w1,   wc1, 130, 64, 17, 2);
    repack_convw_kernel<<<(2 * 8  * B_FLOATS + 255) / 256, 256>>>(w2,   wc2, 64,  64,  8, 2);
    repack_convw_kernel<<<(7 * 8  * B_FLOATS + 255) / 256, 256>>>(w_om, wom, 64, 216, 8, 7);

    dim3 thrM(256);
    // conv1: external inputs -> cvt on; output tf32-rounded
    conv_mma_kernel<<<dim3(8, 16, BB * 2), thrM>>>(
        ref_fea2X_flow, 64, lr_shake_fea, 64, flows, 2,
        wc1, b1, feat1, 64, 17, 2, 1, 1, 1);
    // conv2: input already tf32 -> cvt off; output tf32-rounded
    conv_mma_kernel<<<dim3(8, 16, BB * 2), thrM>>>(
        feat1, 64, (const float*)0, 0, (const float*)0, 0,
        wc2, b2, feat2, 64, 8, 2, 1, 0, 1);
    // conv_om: input already tf32 -> cvt off; raw fp32 output
    conv_mma_kernel<<<dim3(8, 16, BB * 7), thrM>>>(
        feat2, 64, (const float*)0, 0, (const float*)0, 0,
        wom, b_om, omb, 216, 8, 7, 0, 0, 0);

    // modulated deformable conv + lrelu (tf32 MMA accumulate)
    dcn_mma_kernel<<<dim3(8, 16, BB), dim3(16, 8)>>>(ref_fea2X, omb, flows, dcn_b, out);
}

// round 15
// speedup vs baseline: 1.4240x; 1.0730x over previous
#include <cuda_runtime.h>
#include <math.h>

#define HH 128
#define WW 128
#define HW (HH * WW)
#define BB 2

typedef unsigned int u32;

// ---------------- scratch (static device allocations; no runtime alloc) ----
__device__ float g_feat1[BB * 64 * HW];     // after conv1+lrelu
__device__ float g_feat2[BB * 64 * HW];     // after conv2+lrelu
__device__ float g_om[BB * 216 * HW];       // raw conv_om output
__device__ float g_dcnwB[8 * 9 * 8 * 32 * 2];   // dcn weights, MMA B-frag order
// conv weights in per-lane MMA B-frag order: [z][chunk][tap][nt][lane][2]
__device__ float g_wc1[2 * 17 * 2304];
__device__ float g_wc2[2 * 8 * 2304];
__device__ float g_wom[7 * 8 * 2304];

// ---------------- cp.async helpers ----------------------------------------
__device__ __forceinline__ u32 s2u(const void* p) {
    return (u32)__cvta_generic_to_shared(p);
}
__device__ __forceinline__ void cpasync4(u32 dst, const void* src, int srcsize) {
    asm volatile("cp.async.ca.shared.global [%0], [%1], 4, %2;\n"
                 :: "r"(dst), "l"(src), "r"(srcsize));
}
__device__ __forceinline__ void cpasync16(u32 dst, const void* src) {
    asm volatile("cp.async.cg.shared.global [%0], [%1], 16;\n"
                 :: "r"(dst), "l"(src));
}
__device__ __forceinline__ void cpcommit() {
    asm volatile("cp.async.commit_group;\n");
}
template <int N>
__device__ __forceinline__ void cpwait() {
    asm volatile("cp.async.wait_group %0;\n" :: "n"(N));
}

// ---------------- tf32 helpers --------------------------------------------
__device__ __forceinline__ u32 tf32r(float x) {
    u32 u; asm("cvt.rna.tf32.f32 %0, %1;" : "=r"(u) : "f"(x)); return u;
}
__device__ __forceinline__ void mma_tf32(float d[4], const u32 a[4], u32 b0, u32 b1) {
    asm volatile(
        "mma.sync.aligned.m16n8k8.row.col.f32.tf32.tf32.f32 "
        "{%0,%1,%2,%3}, {%4,%5,%6,%7}, {%8,%9}, {%0,%1,%2,%3};\n"
        : "+f"(d[0]), "+f"(d[1]), "+f"(d[2]), "+f"(d[3])
        : "r"(a[0]), "r"(a[1]), "r"(a[2]), "r"(a[3]), "r"(b0), "r"(b1));
}

// ---------------------------------------------------------------------------
// tf32 implicit-GEMM 3x3 conv — R12 structure (A and B cp.async double-
// buffered into smem), with B stored in per-lane fragment order so each
// (tap, nt) B-frag is a single conflict-free LDS.64.
// ---------------------------------------------------------------------------
#define A_PLANE (10 * 20)
#define A_BYTES (8 * A_PLANE * 4)
#define FRAG_CHUNK (9 * 4 * 64)          // 2304 floats per chunk
#define FRAG_BYTES (FRAG_CHUNK * 4)      // 9216 B per buffer
#define NSTGA 6

__global__ void __launch_bounds__(256, 2) conv_mma_kernel(
    const float* __restrict__ inA, int nA,
    const float* __restrict__ inB, int nB,
    const float* __restrict__ inC, int nC,
    const float* __restrict__ wfrag,
    const float* __restrict__ bias,
    float* __restrict__ out, int OC, int chunks, int zTiles, int doLrelu)
{
    const int bz = blockIdx.z;
    const int b  = bz / zTiles;
    const int zi = bz - b * zTiles;
    const int ocBase = zi * 32;

    const int tid  = threadIdx.x;
    const int lane = tid & 31;
    const int warp = tid >> 5;
    const int gid  = lane >> 2;
    const int tig  = lane & 3;

    const int h0 = blockIdx.y * 8;
    const int w0 = blockIdx.x * 16;
    const int ICt = nA + nB + nC;

    __shared__ float sA[2][8][10][20];
    __shared__ float sBf[2][FRAG_CHUNK];

    int  goff[NSTGA];
    int  ginb[NSTGA];
    u32  sofs[NSTGA];
    int  plane[NSTGA];
    int  nElems = 0;
#pragma unroll
    for (int s = 0; s < NSTGA; s++) {
        int i = tid + s * 256;
        if (i < 8 * 10 * 18) {
            int p = i / 180, rem = i - p * 180;
            int r = rem / 18, c = rem - r * 18;
            int gy = h0 + r - 1, gx = w0 + c - 1;
            ginb[s] = (gy >= 0 && gy < HH && gx >= 0 && gx < WW) ? 1 : 0;
            int gyc = min(max(gy, 0), HH - 1);
            int gxc = min(max(gx, 0), WW - 1);
            goff[s]  = gyc * WW + gxc;
            sofs[s]  = (u32)(((p * 10 + r) * 20 + c) * 4);
            plane[s] = p;
            nElems = s + 1;
        }
    }
    const u32 sAbase = s2u(&sA[0][0][0][0]);
    const u32 sBbase = s2u(&sBf[0][0]);
    const float* wz = wfrag + (size_t)zi * chunks * FRAG_CHUNK;

    auto fetchAsync = [&](int buf, int ch) {
#pragma unroll
        for (int s = 0; s < NSTGA; s++) {
            if (s < nElems) {
                int ic = ch * 8 + plane[s];
                const float* base;
                if (ic < nA)            base = inA + ((size_t)(b * nA + ic)) * HW;
                else if (ic < nA + nB)  base = inB + ((size_t)(b * nB + (ic - nA))) * HW;
                else if (ic < ICt)      base = inC + ((size_t)(b * nC + (ic - nA - nB))) * HW;
                else                    base = inA;
                int sz = (ic < ICt && ginb[s]) ? 4 : 0;
                cpasync4(sAbase + (u32)buf * A_BYTES + sofs[s], base + goff[s], sz);
            }
        }
        const float* wsrc = wz + (size_t)ch * FRAG_CHUNK;
#pragma unroll
        for (int s = 0; s < 3; s++) {
            int g = tid + s * 256;
            if (g < FRAG_CHUNK / 4)
                cpasync16(sBbase + (u32)buf * FRAG_BYTES + (u32)g * 16, wsrc + g * 4);
        }
    };

    float acc[4][4];
#pragma unroll
    for (int t = 0; t < 4; t++)
#pragma unroll
        for (int q = 0; q < 4; q++) acc[t][q] = 0.f;

    fetchAsync(0, 0);
    cpcommit();

    int buf = 0;
    for (int ch = 0; ch < chunks; ch++) {
        if (ch + 1 < chunks) {
            fetchAsync(buf ^ 1, ch + 1);
            cpcommit();
            cpwait<1>();
        } else {
            cpwait<0>();
        }
        __syncthreads();

        const float (*PA)[10][20] = sA[buf];
        const float* fragC = &sBf[buf][0];

#pragma unroll
        for (int tap = 0; tap < 9; tap++) {
            const int dy = tap / 3, dx = tap % 3;
            u32 a[4];
            a[0] = tf32r(PA[tig    ][warp + dy][gid     + dx]);
            a[1] = tf32r(PA[tig    ][warp + dy][gid + 8 + dx]);
            a[2] = tf32r(PA[tig + 4][warp + dy][gid     + dx]);
            a[3] = tf32r(PA[tig + 4][warp + dy][gid + 8 + dx]);
#pragma unroll
            for (int t = 0; t < 4; t++) {
                // one LDS.64: {B[tig][t*8+gid], B[tig+4][t*8+gid]}
                float2 bb = *(const float2*)&fragC[((tap * 4 + t) * 32 + lane) * 2];
                mma_tf32(acc[t], a, __float_as_uint(bb.x), __float_as_uint(bb.y));
            }
        }

        __syncthreads();
        buf ^= 1;
    }

    const int py  = h0 + warp;
    const int px0 = w0 + gid;
#pragma unroll
    for (int t = 0; t < 4; t++) {
        int oc = ocBase + t * 8 + 2 * tig;
#pragma unroll
        for (int e = 0; e < 2; e++) {
            int oce = oc + e;
            if (oce < OC) {
                float bv = bias[oce];
                float v0 = acc[t][e]     + bv;
                float v1 = acc[t][e + 2] + bv;
                if (doLrelu) {
                    v0 = (v0 >= 0.f) ? v0 : 0.1f * v0;
                    v1 = (v1 >= 0.f) ? v1 : 0.1f * v1;
                }
                float* dst = out + ((size_t)(b * OC + oce)) * HW + py * WW;
                dst[px0]     = v0;
                dst[px0 + 8] = v1;
            }
        }
    }
}

// ---------------------------------------------------------------------------
// Repack conv weights [oc][ic][tap] -> per-lane B-frag order (R13-proven):
// dst[(((z*chunks + ch)*9 + tap)*4 + nt)*64 + lane*2 + pair]
//   pair p: kk = (lane&3)+4p, oc = z*32 + nt*8 + (lane>>2), ic = ch*8 + kk.
// ---------------------------------------------------------------------------
__global__ void repack_convw_frag(const float* __restrict__ w, float* __restrict__ dst,
                                  int IC, int OC, int chunks, int zTiles)
{
    int total = zTiles * chunks * FRAG_CHUNK;
    int i = blockIdx.x * blockDim.x + threadIdx.x;
    if (i >= total) return;
    int pair = i & 1;
    int t    = i >> 1;
    int lane = t & 31;  t >>= 5;
    int nt   = t & 3;   t >>= 2;
    int tap  = t % 9;   t /= 9;
    int ch   = t % chunks;
    int z    = t / chunks;
    int kk = (lane & 3) + 4 * pair;
    int n  = lane >> 2;
    int ic = ch * 8 + kk;
    int oc = z * 32 + nt * 8 + n;
    float v = 0.f;
    if (ic < IC && oc < OC)
        v = w[((size_t)oc * IC + ic) * 9 + tap];
    u32 u; asm("cvt.rna.tf32.f32 %0, %1;" : "=r"(u) : "f"(v));
    dst[i] = __uint_as_float(u);
}

// ---------------------------------------------------------------------------
// Repack dcn_w [o][g*8+c][k] into per-lane MMA B-fragment order (R12 proven).
// ---------------------------------------------------------------------------
__global__ void repack_dcnwB_kernel(const float* __restrict__ w)
{
    int i = blockIdx.x * blockDim.x + threadIdx.x;
    if (i >= 8 * 9 * 8 * 32 * 2) return;
    int pair = i & 1;
    int t    = i >> 1;
    int lane = t & 31;  t >>= 5;
    int nt   = t & 7;   t >>= 3;
    int k    = t % 9;
    int g    = t / 9;
    int c  = (lane & 3) + 4 * pair;
    int oc = nt * 8 + (lane >> 2);
    float v = w[(size_t)oc * 576 + (g * 8 + c) * 9 + k];
    u32 u; asm("cvt.rna.tf32.f32 %0, %1;" : "=r"(u) : "f"(v));
    g_dcnwB[i] = __uint_as_float(u);
}

// ---------------------------------------------------------------------------
// Modulated deformable conv with tf32 MMA accumulate (R12 proven, unchanged).
// ---------------------------------------------------------------------------
__global__ void __launch_bounds__(128, 2) dcn_mma_kernel(
    const float* __restrict__ feat,
    const float* __restrict__ om,
    const float* __restrict__ flows,
    const float* __restrict__ bias,
    float* __restrict__ out)
{
    const int b  = blockIdx.z;
    const int tx = threadIdx.x;
    const int ty = threadIdx.y;
    const int tid = ty * 16 + tx;
    const int lane = tid & 31;
    const int warpid = tid >> 5;
    const int gid = lane >> 2;
    const int tig = lane & 3;
    const int h = blockIdx.y * 8 + ty;
    const int w = blockIdx.x * 16 + tx;
    const int pix = h * WW + w;

    __shared__ float sVal[4][9][32][9];

    float acc[2][8][4];
#pragma unroll
    for (int m = 0; m < 2; m++)
#pragma unroll
        for (int n = 0; n < 8; n++)
#pragma unroll
            for (int q = 0; q < 4; q++) acc[m][n][q] = 0.f;

    const float flowX = flows[(b * 2 + 0) * HW + pix];
    const float flowY = flows[(b * 2 + 1) * HW + pix];
    const float* omb = om   + (size_t)b * 216 * HW;
    const float* fb  = feat + (size_t)b * 64 * HW;

    for (int g = 0; g < 8; g++) {
        float offv[18], mskv[9];
#pragma unroll
        for (int q = 0; q < 18; q++)
            offv[q] = omb[((size_t)(g * 18 + q)) * HW + pix];
#pragma unroll
        for (int q = 0; q < 9; q++)
            mskv[q] = omb[((size_t)(144 + g * 9 + q)) * HW + pix];

        const float* fgc = fb + (g * 8) * HW;

#pragma unroll
        for (int k = 0; k < 9; k++) {
            const int kh = k / 3, kw = k - kh * 3;
            float dy = offv[2 * k + 0] + flowY;
            float dx = offv[2 * k + 1] + flowX;
            float mv = mskv[k];
            mv = 1.f / (1.f + __expf(-mv));

            float y = (float)h - 1.f + (float)kh + dy;
            float x = (float)w - 1.f + (float)kw + dx;
            float y0f = floorf(y), x0f = floorf(x);
            int y0 = (int)y0f, x0 = (int)x0f;
            float fy = y - y0f, fx = x - x0f;

            float w00 = (1.f - fy) * (1.f - fx);
            float w01 = (1.f - fy) * fx;
            float w10 = fy * (1.f - fx);
            float w11 = fy * fx;

            const bool iy0 = (y0 >= 0) && (y0 < HH);
            const bool iy1 = (y0 + 1 >= 0) && (y0 + 1 < HH);
            const bool ix0 = (x0 >= 0) && (x0 < WW);
            const bool ix1 = (x0 + 1 >= 0) && (x0 + 1 < WW);
            w00 = (iy0 && ix0) ? w00 * mv : 0.f;
            w01 = (iy0 && ix1) ? w01 * mv : 0.f;
            w10 = (iy1 && ix0) ? w10 * mv : 0.f;
            w11 = (iy1 && ix1) ? w11 * mv : 0.f;

            int yc0 = min(max(y0, 0), HH - 1);
            int yc1 = min(max(y0 + 1, 0), HH - 1);
            int xc0 = min(max(x0, 0), WW - 1);
            int xc1 = min(max(x0 + 1, 0), WW - 1);
            int i00 = yc0 * WW + xc0, i01 = yc0 * WW + xc1;
            int i10 = yc1 * WW + xc0, i11 = yc1 * WW + xc1;

#pragma unroll
            for (int c = 0; c < 8; c++) {
                const float* fc = fgc + c * HW;
                float val = w00 * fc[i00] + w01 * fc[i01]
                          + w10 * fc[i10] + w11 * fc[i11];
                sVal[warpid][k][lane][c] = __uint_as_float(tf32r(val));
            }
        }
        __syncwarp();

        const float* fragBase = g_dcnwB + (size_t)g * 9 * 8 * 64;
#pragma unroll
        for (int k = 0; k < 9; k++) {
            const float (*V)[9] = sVal[warpid][k];
            u32 a0[4], a1[4];
            a0[0] = __float_as_uint(V[gid     ][tig    ]);
            a0[1] = __float_as_uint(V[gid + 8 ][tig    ]);
            a0[2] = __float_as_uint(V[gid     ][tig + 4]);
            a0[3] = __float_as_uint(V[gid + 8 ][tig + 4]);
            a1[0] = __float_as_uint(V[gid + 16][tig    ]);
            a1[1] = __float_as_uint(V[gid + 24][tig    ]);
            a1[2] = __float_as_uint(V[gid + 16][tig + 4]);
            a1[3] = __float_as_uint(V[gid + 24][tig + 4]);
#pragma unroll
            for (int nt = 0; nt < 8; nt++) {
                float2 bb = *(const float2*)&fragBase[((k * 8 + nt) * 32 + lane) * 2];
                u32 b0 = __float_as_uint(bb.x);
                u32 b1 = __float_as_uint(bb.y);
                mma_tf32(acc[0][nt], a0, b0, b1);
                mma_tf32(acc[1][nt], a1, b0, b1);
            }
        }
        __syncwarp();
    }

    const int h0 = blockIdx.y * 8;
    const int w0 = blockIdx.x * 16;
#pragma unroll
    for (int m = 0; m < 2; m++) {
        int r0 = warpid * 32 + m * 16 + gid;
        int r1 = r0 + 8;
        int hA = h0 + (r0 >> 4), wA = w0 + (r0 & 15);
        int hB = h0 + (r1 >> 4), wB2 = w0 + (r1 & 15);
#pragma unroll
        for (int nt = 0; nt < 8; nt++) {
            int oc0 = nt * 8 + 2 * tig;
#pragma unroll
            for (int e = 0; e < 2; e++) {
                int oc = oc0 + e;
                float bv = bias[oc];
                float vA = acc[m][nt][e]     + bv;
                float vB = acc[m][nt][e + 2] + bv;
                vA = (vA >= 0.f) ? vA : 0.1f * vA;
                vB = (vB >= 0.f) ? vB : 0.1f * vB;
                out[((size_t)(b * 64 + oc)) * HW + hA * WW + wA]  = vA;
                out[((size_t)(b * 64 + oc)) * HW + hB * WW + wB2] = vB;
            }
        }
    }
}

// ---------------------------------------------------------------------------
extern "C" void kernel_launch(void* const* d_in, const int* in_sizes, int n_in,
                              void* d_out, int out_size)
{
    const float* ref_fea2X      = (const float*)d_in[0];
    const float* ref_fea2X_flow = (const float*)d_in[1];
    const float* lr_shake_fea   = (const float*)d_in[2];
    const float* flows          = (const float*)d_in[3];
    const float* w1             = (const float*)d_in[4];
    const float* b1             = (const float*)d_in[5];
    const float* w2             = (const float*)d_in[6];
    const float* b2             = (const float*)d_in[7];
    const float* w_om           = (const float*)d_in[8];
    const float* b_om           = (const float*)d_in[9];
    const float* dcn_w          = (const float*)d_in[10];
    const float* dcn_b          = (const float*)d_in[11];
    float* out = (float*)d_out;

    float *feat1, *feat2, *omb, *wc1, *wc2, *wom;
    cudaGetSymbolAddress((void**)&feat1, g_feat1);
    cudaGetSymbolAddress((void**)&feat2, g_feat2);
    cudaGetSymbolAddress((void**)&omb,   g_om);
    cudaGetSymbolAddress((void**)&wc1,   g_wc1);
    cudaGetSymbolAddress((void**)&wc2,   g_wc2);
    cudaGetSymbolAddress((void**)&wom,   g_wom);

    // weight repacks (independent of activations)
    repack_dcnwB_kernel<<<(8 * 9 * 8 * 32 * 2 + 255) / 256, 256>>>(dcn_w);
    repack_convw_frag<<<(2 * 17 * FRAG_CHUNK + 255) / 256, 256>>>(w1,   wc1, 130, 64, 17, 2);
    repack_convw_frag<<<(2 * 8  * FRAG_CHUNK + 255) / 256, 256>>>(w2,   wc2, 64,  64,  8, 2);
    repack_convw_frag<<<(7 * 8  * FRAG_CHUNK + 255) / 256, 256>>>(w_om, wom, 64, 216, 8, 7);

    dim3 thrM(256);
    // conv1: concat(ref_fea2X_flow, lr_shake_fea, flows) 130 -> 64, lrelu
    conv_mma_kernel<<<dim3(8, 16, BB * 2), thrM>>>(
        ref_fea2X_flow, 64, lr_shake_fea, 64, flows, 2,
        wc1, b1, feat1, 64, 17, 2, 1);
    // conv2: 64 -> 64, lrelu
    conv_mma_kernel<<<dim3(8, 16, BB * 2), thrM>>>(
        feat1, 64, (const float*)0, 0, (const float*)0, 0,
        wc2, b2, feat2, 64, 8, 2, 1);
    // conv_om: 64 -> 216, raw
    conv_mma_kernel<<<dim3(8, 16, BB * 7), thrM>>>(
        feat2, 64, (const float*)0, 0, (const float*)0, 0,
        wom, b_om, omb, 216, 8, 7, 0);

    // modulated deformable conv + lrelu (tf32 MMA accumulate)
    dcn_mma_kernel<<<dim3(8, 16, BB), dim3(16, 8)>>>(ref_fea2X, omb, flows, dcn_b, out);
}

// round 17
// speedup vs baseline: 1.6945x; 1.1899x over previous
#include <cuda_runtime.h>
#include <math.h>

#define HH 128
#define WW 128
#define HW (HH * WW)
#define BB 2

typedef unsigned int u32;

// ---------------- scratch (static device allocations; no runtime alloc) ----
__device__ float g_feat1[BB * 64 * HW];     // after conv1+lrelu
__device__ float g_feat2[BB * 64 * HW];     // after conv2+lrelu
__device__ float g_om[BB * 216 * HW];       // raw conv_om output
__device__ float g_dcnwB[8 * 9 * 8 * 32 * 2];   // dcn weights, MMA B-frag order
// conv weights in per-lane MMA B-frag order: [z][chunk][tap][nt8][lane][2]
#define FRAG_CHUNK (9 * 8 * 64)          // 4608 floats per chunk (64 oc)
__device__ float g_wc1[1 * 17 * FRAG_CHUNK];
__device__ float g_wc2[1 * 8  * FRAG_CHUNK];
__device__ float g_wom[4 * 8  * FRAG_CHUNK];

// ---------------- cp.async helpers ----------------------------------------
__device__ __forceinline__ u32 s2u(const void* p) {
    return (u32)__cvta_generic_to_shared(p);
}
__device__ __forceinline__ void cpasync4(u32 dst, const void* src, int srcsize) {
    asm volatile("cp.async.ca.shared.global [%0], [%1], 4, %2;\n"
                 :: "r"(dst), "l"(src), "r"(srcsize));
}
__device__ __forceinline__ void cpasync16(u32 dst, const void* src) {
    asm volatile("cp.async.cg.shared.global [%0], [%1], 16;\n"
                 :: "r"(dst), "l"(src));
}
__device__ __forceinline__ void cpcommit() {
    asm volatile("cp.async.commit_group;\n");
}
template <int N>
__device__ __forceinline__ void cpwait() {
    asm volatile("cp.async.wait_group %0;\n" :: "n"(N));
}

// ---------------- tf32 helpers --------------------------------------------
__device__ __forceinline__ u32 tf32r(float x) {
    u32 u; asm("cvt.rna.tf32.f32 %0, %1;" : "=r"(u) : "f"(x)); return u;
}
__device__ __forceinline__ void mma_tf32(float d[4], const u32 a[4], u32 b0, u32 b1) {
    asm volatile(
        "mma.sync.aligned.m16n8k8.row.col.f32.tf32.tf32.f32 "
        "{%0,%1,%2,%3}, {%4,%5,%6,%7}, {%8,%9}, {%0,%1,%2,%3};\n"
        : "+f"(d[0]), "+f"(d[1]), "+f"(d[2]), "+f"(d[3])
        : "r"(a[0]), "r"(a[1]), "r"(a[2]), "r"(a[3]), "r"(b0), "r"(b1));
}

// ---------------------------------------------------------------------------
// tf32 implicit-GEMM 3x3 conv. 64 output channels per block (8 n8 tiles).
// DYNAMIC shared memory (49,664 B > 48 KB static limit):
//   [0,               2*A_BYTES)          : sA double buffer
//   [2*A_BYTES,       2*A_BYTES+2*FRAG_B) : sBf double buffer
// ---------------------------------------------------------------------------
#define A_PLANE (10 * 20)
#define A_BYTES (8 * A_PLANE * 4)            // 6400 B per buffer
#define FRAG_BYTES (FRAG_CHUNK * 4)          // 18432 B per buffer
#define CONV_SMEM (2 * A_BYTES + 2 * FRAG_BYTES)   // 49664 B
#define NSTGA 6

__global__ void __launch_bounds__(256, 2) conv_mma_kernel(
    const float* __restrict__ inA, int nA,
    const float* __restrict__ inB, int nB,
    const float* __restrict__ inC, int nC,
    const float* __restrict__ wfrag,
    const float* __restrict__ bias,
    float* __restrict__ out, int OC, int chunks, int zTiles, int doLrelu)
{
    extern __shared__ float smem[];
    // sA[buf][plane][row][col] : buf*1600 + ((p*10+r)*20+c)
    float* sA  = smem;
    float* sBf = smem + 2 * 8 * A_PLANE;

    const int bz = blockIdx.z;
    const int b  = bz / zTiles;
    const int zi = bz - b * zTiles;
    const int ocBase = zi * 64;

    const int tid  = threadIdx.x;
    const int lane = tid & 31;
    const int warp = tid >> 5;
    const int gid  = lane >> 2;
    const int tig  = lane & 3;

    const int h0 = blockIdx.y * 8;
    const int w0 = blockIdx.x * 16;
    const int ICt = nA + nB + nC;

    int  goff[NSTGA];
    int  ginb[NSTGA];
    u32  sofs[NSTGA];
    int  plane[NSTGA];
    int  nElems = 0;
#pragma unroll
    for (int s = 0; s < NSTGA; s++) {
        int i = tid + s * 256;
        if (i < 8 * 10 * 18) {
            int p = i / 180, rem = i - p * 180;
            int r = rem / 18, c = rem - r * 18;
            int gy = h0 + r - 1, gx = w0 + c - 1;
            ginb[s] = (gy >= 0 && gy < HH && gx >= 0 && gx < WW) ? 1 : 0;
            int gyc = min(max(gy, 0), HH - 1);
            int gxc = min(max(gx, 0), WW - 1);
            goff[s]  = gyc * WW + gxc;
            sofs[s]  = (u32)(((p * 10 + r) * 20 + c) * 4);
            plane[s] = p;
            nElems = s + 1;
        }
    }
    const u32 sAbase = s2u(sA);
    const u32 sBbase = s2u(sBf);
    const float* wz = wfrag + (size_t)zi * chunks * FRAG_CHUNK;

    auto fetchAsync = [&](int buf, int ch) {
#pragma unroll
        for (int s = 0; s < NSTGA; s++) {
            if (s < nElems) {
                int ic = ch * 8 + plane[s];
                const float* base;
                if (ic < nA)            base = inA + ((size_t)(b * nA + ic)) * HW;
                else if (ic < nA + nB)  base = inB + ((size_t)(b * nB + (ic - nA))) * HW;
                else if (ic < ICt)      base = inC + ((size_t)(b * nC + (ic - nA - nB))) * HW;
                else                    base = inA;
                int sz = (ic < ICt && ginb[s]) ? 4 : 0;
                cpasync4(sAbase + (u32)buf * A_BYTES + sofs[s], base + goff[s], sz);
            }
        }
        const float* wsrc = wz + (size_t)ch * FRAG_CHUNK;
#pragma unroll
        for (int s = 0; s < 5; s++) {
            int g = tid + s * 256;
            if (g < FRAG_CHUNK / 4)
                cpasync16(sBbase + (u32)buf * FRAG_BYTES + (u32)g * 16, wsrc + g * 4);
        }
    };

    float acc[8][4];
#pragma unroll
    for (int t = 0; t < 8; t++)
#pragma unroll
        for (int q = 0; q < 4; q++) acc[t][q] = 0.f;

    fetchAsync(0, 0);
    cpcommit();

    int buf = 0;
    for (int ch = 0; ch < chunks; ch++) {
        if (ch + 1 < chunks) {
            fetchAsync(buf ^ 1, ch + 1);
            cpcommit();
            cpwait<1>();
        } else {
            cpwait<0>();
        }
        __syncthreads();

        const float* PA = sA + buf * 8 * A_PLANE;   // [plane][10][20]
        const float* fragC = sBf + buf * FRAG_CHUNK;

#pragma unroll
        for (int tap = 0; tap < 9; tap++) {
            const int dy = tap / 3, dx = tap % 3;
            u32 a[4];
            a[0] = tf32r(PA[(tig      * 10 + warp + dy) * 20 + gid     + dx]);
            a[1] = tf32r(PA[(tig      * 10 + warp + dy) * 20 + gid + 8 + dx]);
            a[2] = tf32r(PA[((tig + 4) * 10 + warp + dy) * 20 + gid     + dx]);
            a[3] = tf32r(PA[((tig + 4) * 10 + warp + dy) * 20 + gid + 8 + dx]);
#pragma unroll
            for (int t = 0; t < 8; t++) {
                // one LDS.64: {B[tig][t*8+gid], B[tig+4][t*8+gid]}
                float2 bb = *(const float2*)&fragC[((tap * 8 + t) * 32 + lane) * 2];
                mma_tf32(acc[t], a, __float_as_uint(bb.x), __float_as_uint(bb.y));
            }
        }

        __syncthreads();
        buf ^= 1;
    }

    const int py  = h0 + warp;
    const int px0 = w0 + gid;
#pragma unroll
    for (int t = 0; t < 8; t++) {
        int oc = ocBase + t * 8 + 2 * tig;
#pragma unroll
        for (int e = 0; e < 2; e++) {
            int oce = oc + e;
            if (oce < OC) {
                float bv = bias[oce];
                float v0 = acc[t][e]     + bv;
                float v1 = acc[t][e + 2] + bv;
                if (doLrelu) {
                    v0 = (v0 >= 0.f) ? v0 : 0.1f * v0;
                    v1 = (v1 >= 0.f) ? v1 : 0.1f * v1;
                }
                float* dst = out + ((size_t)(b * OC + oce)) * HW + py * WW;
                dst[px0]     = v0;
                dst[px0 + 8] = v1;
            }
        }
    }
}

// ---------------------------------------------------------------------------
// Repack conv weights [oc][ic][tap] -> per-lane B-frag order, 64-oc tiles:
// dst[(((z*chunks + ch)*9 + tap)*8 + nt)*64 + lane*2 + pair]
//   pair p: kk = (lane&3)+4p, oc = z*64 + nt*8 + (lane>>2), ic = ch*8 + kk.
// ---------------------------------------------------------------------------
__global__ void repack_convw_frag(const float* __restrict__ w, float* __restrict__ dst,
                                  int IC, int OC, int chunks, int zTiles)
{
    int total = zTiles * chunks * FRAG_CHUNK;
    int i = blockIdx.x * blockDim.x + threadIdx.x;
    if (i >= total) return;
    int pair = i & 1;
    int t    = i >> 1;
    int lane = t & 31;  t >>= 5;
    int nt   = t & 7;   t >>= 3;
    int tap  = t % 9;   t /= 9;
    int ch   = t % chunks;
    int z    = t / chunks;
    int kk = (lane & 3) + 4 * pair;
    int n  = lane >> 2;
    int ic = ch * 8 + kk;
    int oc = z * 64 + nt * 8 + n;
    float v = 0.f;
    if (ic < IC && oc < OC)
        v = w[((size_t)oc * IC + ic) * 9 + tap];
    u32 u; asm("cvt.rna.tf32.f32 %0, %1;" : "=r"(u) : "f"(v));
    dst[i] = __uint_as_float(u);
}

// ---------------------------------------------------------------------------
// Repack dcn_w [o][g*8+c][k] into per-lane MMA B-fragment order (R12 proven).
// ---------------------------------------------------------------------------
__global__ void repack_dcnwB_kernel(const float* __restrict__ w)
{
    int i = blockIdx.x * blockDim.x + threadIdx.x;
    if (i >= 8 * 9 * 8 * 32 * 2) return;
    int pair = i & 1;
    int t    = i >> 1;
    int lane = t & 31;  t >>= 5;
    int nt   = t & 7;   t >>= 3;
    int k    = t % 9;
    int g    = t / 9;
    int c  = (lane & 3) + 4 * pair;
    int oc = nt * 8 + (lane >> 2);
    float v = w[(size_t)oc * 576 + (g * 8 + c) * 9 + k];
    u32 u; asm("cvt.rna.tf32.f32 %0, %1;" : "=r"(u) : "f"(v));
    g_dcnwB[i] = __uint_as_float(u);
}

// ---------------------------------------------------------------------------
// Modulated deformable conv with tf32 MMA accumulate (R12 proven, unchanged).
// ---------------------------------------------------------------------------
__global__ void __launch_bounds__(128, 2) dcn_mma_kernel(
    const float* __restrict__ feat,
    const float* __restrict__ om,
    const float* __restrict__ flows,
    const float* __restrict__ bias,
    float* __restrict__ out)
{
    const int b  = blockIdx.z;
    const int tx = threadIdx.x;
    const int ty = threadIdx.y;
    const int tid = ty * 16 + tx;
    const int lane = tid & 31;
    const int warpid = tid >> 5;
    const int gid = lane >> 2;
    const int tig = lane & 3;
    const int h = blockIdx.y * 8 + ty;
    const int w = blockIdx.x * 16 + tx;
    const int pix = h * WW + w;

    __shared__ float sVal[4][9][32][9];

    float acc[2][8][4];
#pragma unroll
    for (int m = 0; m < 2; m++)
#pragma unroll
        for (int n = 0; n < 8; n++)
#pragma unroll
            for (int q = 0; q < 4; q++) acc[m][n][q] = 0.f;

    const float flowX = flows[(b * 2 + 0) * HW + pix];
    const float flowY = flows[(b * 2 + 1) * HW + pix];
    const float* omb = om   + (size_t)b * 216 * HW;
    const float* fb  = feat + (size_t)b * 64 * HW;

    for (int g = 0; g < 8; g++) {
        float offv[18], mskv[9];
#pragma unroll
        for (int q = 0; q < 18; q++)
            offv[q] = omb[((size_t)(g * 18 + q)) * HW + pix];
#pragma unroll
        for (int q = 0; q < 9; q++)
            mskv[q] = omb[((size_t)(144 + g * 9 + q)) * HW + pix];

        const float* fgc = fb + (g * 8) * HW;

#pragma unroll
        for (int k = 0; k < 9; k++) {
            const int kh = k / 3, kw = k - kh * 3;
            float dy = offv[2 * k + 0] + flowY;
            float dx = offv[2 * k + 1] + flowX;
            float mv = mskv[k];
            mv = 1.f / (1.f + __expf(-mv));

            float y = (float)h - 1.f + (float)kh + dy;
            float x = (float)w - 1.f + (float)kw + dx;
            float y0f = floorf(y), x0f = floorf(x);
            int y0 = (int)y0f, x0 = (int)x0f;
            float fy = y - y0f, fx = x - x0f;

            float w00 = (1.f - fy) * (1.f - fx);
            float w01 = (1.f - fy) * fx;
            float w10 = fy * (1.f - fx);
            float w11 = fy * fx;

            const bool iy0 = (y0 >= 0) && (y0 < HH);
            const bool iy1 = (y0 + 1 >= 0) && (y0 + 1 < HH);
            const bool ix0 = (x0 >= 0) && (x0 < WW);
            const bool ix1 = (x0 + 1 >= 0) && (x0 + 1 < WW);
            w00 = (iy0 && ix0) ? w00 * mv : 0.f;
            w01 = (iy0 && ix1) ? w01 * mv : 0.f;
            w10 = (iy1 && ix0) ? w10 * mv : 0.f;
            w11 = (iy1 && ix1) ? w11 * mv : 0.f;

            int yc0 = min(max(y0, 0), HH - 1);
            int yc1 = min(max(y0 + 1, 0), HH - 1);
            int xc0 = min(max(x0, 0), WW - 1);
            int xc1 = min(max(x0 + 1, 0), WW - 1);
            int i00 = yc0 * WW + xc0, i01 = yc0 * WW + xc1;
            int i10 = yc1 * WW + xc0, i11 = yc1 * WW + xc1;

#pragma unroll
            for (int c = 0; c < 8; c++) {
                const float* fc = fgc + c * HW;
                float val = w00 * fc[i00] + w01 * fc[i01]
                          + w10 * fc[i10] + w11 * fc[i11];
                sVal[warpid][k][lane][c] = __uint_as_float(tf32r(val));
            }
        }
        __syncwarp();

        const float* fragBase = g_dcnwB + (size_t)g * 9 * 8 * 64;
#pragma unroll
        for (int k = 0; k < 9; k++) {
            const float (*V)[9] = sVal[warpid][k];
            u32 a0[4], a1[4];
            a0[0] = __float_as_uint(V[gid     ][tig    ]);
            a0[1] = __float_as_uint(V[gid + 8 ][tig    ]);
            a0[2] = __float_as_uint(V[gid     ][tig + 4]);
            a0[3] = __float_as_uint(V[gid + 8 ][tig + 4]);
            a1[0] = __float_as_uint(V[gid + 16][tig    ]);
            a1[1] = __float_as_uint(V[gid + 24][tig    ]);
            a1[2] = __float_as_uint(V[gid + 16][tig + 4]);
            a1[3] = __float_as_uint(V[gid + 24][tig + 4]);
#pragma unroll
            for (int nt = 0; nt < 8; nt++) {
                float2 bb = *(const float2*)&fragBase[((k * 8 + nt) * 32 + lane) * 2];
                u32 b0 = __float_as_uint(bb.x);
                u32 b1 = __float_as_uint(bb.y);
                mma_tf32(acc[0][nt], a0, b0, b1);
                mma_tf32(acc[1][nt], a1, b0, b1);
            }
        }
        __syncwarp();
    }

    const int h0 = blockIdx.y * 8;
    const int w0 = blockIdx.x * 16;
#pragma unroll
    for (int m = 0; m < 2; m++) {
        int r0 = warpid * 32 + m * 16 + gid;
        int r1 = r0 + 8;
        int hA = h0 + (r0 >> 4), wA = w0 + (r0 & 15);
        int hB = h0 + (r1 >> 4), wB2 = w0 + (r1 & 15);
#pragma unroll
        for (int nt = 0; nt < 8; nt++) {
            int oc0 = nt * 8 + 2 * tig;
#pragma unroll
            for (int e = 0; e < 2; e++) {
                int oc = oc0 + e;
                float bv = bias[oc];
                float vA = acc[m][nt][e]     + bv;
                float vB = acc[m][nt][e + 2] + bv;
                vA = (vA >= 0.f) ? vA : 0.1f * vA;
                vB = (vB >= 0.f) ? vB : 0.1f * vB;
                out[((size_t)(b * 64 + oc)) * HW + hA * WW + wA]  = vA;
                out[((size_t)(b * 64 + oc)) * HW + hB * WW + wB2] = vB;
            }
        }
    }
}

// ---------------------------------------------------------------------------
extern "C" void kernel_launch(void* const* d_in, const int* in_sizes, int n_in,
                              void* d_out, int out_size)
{
    const float* ref_fea2X      = (const float*)d_in[0];
    const float* ref_fea2X_flow = (const float*)d_in[1];
    const float* lr_shake_fea   = (const float*)d_in[2];
    const float* flows          = (const float*)d_in[3];
    const float* w1             = (const float*)d_in[4];
    const float* b1             = (const float*)d_in[5];
    const float* w2             = (const float*)d_in[6];
    const float* b2             = (const float*)d_in[7];
    const float* w_om           = (const float*)d_in[8];
    const float* b_om           = (const float*)d_in[9];
    const float* dcn_w          = (const float*)d_in[10];
    const float* dcn_b          = (const float*)d_in[11];
    float* out = (float*)d_out;

    float *feat1, *feat2, *omb, *wc1, *wc2, *wom;
    cudaGetSymbolAddress((void**)&feat1, g_feat1);
    cudaGetSymbolAddress((void**)&feat2, g_feat2);
    cudaGetSymbolAddress((void**)&omb,   g_om);
    cudaGetSymbolAddress((void**)&wc1,   g_wc1);
    cudaGetSymbolAddress((void**)&wc2,   g_wc2);
    cudaGetSymbolAddress((void**)&wom,   g_wom);

    // raise dynamic smem limit for the conv kernel (host state, no alloc;
    // immediate effect — safe under graph capture)
    cudaFuncSetAttribute(conv_mma_kernel,
                         cudaFuncAttributeMaxDynamicSharedMemorySize, CONV_SMEM);

    // weight repacks (independent of activations)
    repack_dcnwB_kernel<<<(8 * 9 * 8 * 32 * 2 + 255) / 256, 256>>>(dcn_w);
    repack_convw_frag<<<(1 * 17 * FRAG_CHUNK + 255) / 256, 256>>>(w1,   wc1, 130, 64, 17, 1);
    repack_convw_frag<<<(1 * 8  * FRAG_CHUNK + 255) / 256, 256>>>(w2,   wc2, 64,  64,  8, 1);
    repack_convw_frag<<<(4 * 8  * FRAG_CHUNK + 255) / 256, 256>>>(w_om, wom, 64, 216, 8, 4);

    dim3 thrM(256);
    // conv1: concat(ref_fea2X_flow, lr_shake_fea, flows) 130 -> 64, lrelu
    conv_mma_kernel<<<dim3(8, 16, BB * 1), thrM, CONV_SMEM>>>(
        ref_fea2X_flow, 64, lr_shake_fea, 64, flows, 2,
        wc1, b1, feat1, 64, 17, 1, 1);
    // conv2: 64 -> 64, lrelu
    conv_mma_kernel<<<dim3(8, 16, BB * 1), thrM, CONV_SMEM>>>(
        feat1, 64, (const float*)0, 0, (const float*)0, 0,
        wc2, b2, feat2, 64, 8, 1, 1);
    // conv_om: 64 -> 216, raw
    conv_mma_kernel<<<dim3(8, 16, BB * 4), thrM, CONV_SMEM>>>(
        feat2, 64, (const float*)0, 0, (const float*)0, 0,
        wom, b_om, omb, 216, 8, 4, 0);

    // modulated deformable conv + lrelu (tf32 MMA accumulate)
    dcn_mma_kernel<<<dim3(8, 16, BB), dim3(16, 8)>>>(ref_fea2X, omb, flows, dcn_b, out);
}